// round 13
// baseline (speedup 1.0000x reference)
#include <cuda_runtime.h>
#include <cuda_fp16.h>

#define NN 50000
#define NE 800000
#define HN 25000   // node pairs: pair p handles nodes p and p+HN
#define PREP_GRID 148

// Scratch (device globals — no allocation allowed in kernel_launch).
// g_Z4: per-node Z padded to 320B (20 float4): float4 index f=2d+h holds fp16
// Z[d][h*8..h*8+7], d=0..7 from nnW, d=8 from nnb; f=18,19 unused padding.
__device__ float4 g_Z4[(size_t)NN * 20];
__device__ float  g_agg[2][(size_t)NN * 16];  // ping-pong node feature buffers
// Packed per-edge data (built once per launch by pack_kernel):
// g_pc[2e+hi] = 4 pre-broadcast half2 coefficients {c,c} for d = hi,2+hi,4+hi,6+hi
__device__ float4 g_pc[(size_t)NE * 2];
__device__ int2   g_idx[(size_t)NE];          // (src, dst)

// ---- packed f32x2 helpers (FFMA2: 2 fp32 FMAs per instruction, exact) ----
__device__ __forceinline__ unsigned long long f2pack(float lo, float hi) {
    unsigned long long d;
    asm("mov.b64 %0, {%1, %2};" : "=l"(d) : "f"(lo), "f"(hi));
    return d;
}
__device__ __forceinline__ void f2unpack(unsigned long long v, float& lo, float& hi) {
    asm("mov.b64 {%0, %1}, %2;" : "=f"(lo), "=f"(hi) : "l"(v));
}
__device__ __forceinline__ unsigned long long ffma2(
    unsigned long long a, unsigned long long b, unsigned long long c) {
    unsigned long long d;
    asm("fma.rn.f32x2 %0, %1, %2, %3;" : "=l"(d) : "l"(a), "l"(b), "l"(c));
    return d;
}

// ---------------------------------------------------------------------------
// pack: one-time conversion of edge_attr -> pre-broadcast fp16 coefficient
// groups + packed (src,dst). Removes all per-layer staging from edge_kernel.
// ---------------------------------------------------------------------------
__global__ void __launch_bounds__(256) pack_kernel(
    const int* __restrict__ ei, const float* __restrict__ ea)
{
    const int e = blockIdx.x * 256 + threadIdx.x;
    if (e >= NE) return;
    const float4 a = ((const float4*)ea)[(size_t)e * 2 + 0];  // c0..c3
    const float4 b = ((const float4*)ea)[(size_t)e * 2 + 1];  // c4..c7

    __half2 h0[4] = { __float2half2_rn(a.x), __float2half2_rn(a.z),
                      __float2half2_rn(b.x), __float2half2_rn(b.z) };  // hi=0: c0,c2,c4,c6
    __half2 h1[4] = { __float2half2_rn(a.y), __float2half2_rn(a.w),
                      __float2half2_rn(b.y), __float2half2_rn(b.w) };  // hi=1: c1,c3,c5,c7
    g_pc[(size_t)e * 2 + 0] = *(float4*)h0;
    g_pc[(size_t)e * 2 + 1] = *(float4*)h1;
    g_idx[e] = make_int2(ei[e], ei[NE + e]);
}

// ---------------------------------------------------------------------------
// prep: persistent-style — exactly 148 blocks (1/SM), weights staged ONCE
// per block, then grid-stride over 2 chunks of 128 pairs. Warp-uniform
// roles: warp w -> role r = w&1, pair-group pg = w>>1 (4 groups x 32 lanes).
// Pair p = nodes (p, p+HN); r=0 computes Z rows d=0..4, r=1 computes Z rows
// d=5..8 + root term, both for BOTH nodes (weight quad amortized over 2
// nodes). f32x2 packed FMA, exact fp32 math.
// ---------------------------------------------------------------------------
__global__ void __launch_bounds__(256) prep_kernel(
    const float* __restrict__ x0, int layer,
    const float* __restrict__ nnW, const float* __restrict__ nnb,
    const float* __restrict__ rootW, const float* __restrict__ bias)
{
    __shared__ float4 sWB[576];   // [0,512): nnW (8 x 256 floats), [512,576): nnb
    __shared__ float4 sR[64];     // rootW
    __shared__ float4 sBias[4];   // bias

    const int tid = threadIdx.x;
    const float4* W4  = (const float4*)(nnW   + (size_t)layer * 2048);
    const float4* B4  = (const float4*)(nnb   + (size_t)layer * 256);
    const float4* R4  = (const float4*)(rootW + (size_t)layer * 256);
    const float4* Bi4 = (const float4*)(bias  + (size_t)layer * 16);

    #pragma unroll
    for (int j = tid; j < 512; j += 256) sWB[j] = W4[j];
    if (tid < 64) { sWB[512 + tid] = B4[tid]; sR[tid] = R4[tid]; }
    if (tid < 4)  sBias[tid] = Bi4[tid];
    __syncthreads();

    const int warp = tid >> 5;
    const int lane = tid & 31;
    const int r    = warp & 1;
    const int pg   = warp >> 1;   // 0..3

    const float* xin = (layer == 0) ? x0 : g_agg[(layer - 1) & 1];

    #pragma unroll 1
    for (int c = 0; c < 2; c++) {
        const int p = (c * PREP_GRID + blockIdx.x) * 128 + pg * 32 + lane;
        if (p >= HN) continue;
        const int n0 = p;
        const int n1 = p + HN;

        // load + relu + pack {x,x} for both nodes
        unsigned long long xa[16], xb[16];
        {
            const float4* xr0 = (const float4*)(xin + (size_t)n0 * 16);
            const float4* xr1 = (const float4*)(xin + (size_t)n1 * 16);
            #pragma unroll
            for (int cc = 0; cc < 4; cc++) {
                float4 v0 = xr0[cc];
                float4 v1 = xr1[cc];
                if (layer) {
                    v0.x = fmaxf(v0.x, 0.f); v0.y = fmaxf(v0.y, 0.f);
                    v0.z = fmaxf(v0.z, 0.f); v0.w = fmaxf(v0.w, 0.f);
                    v1.x = fmaxf(v1.x, 0.f); v1.y = fmaxf(v1.y, 0.f);
                    v1.z = fmaxf(v1.z, 0.f); v1.w = fmaxf(v1.w, 0.f);
                }
                xa[4*cc+0] = f2pack(v0.x, v0.x); xa[4*cc+1] = f2pack(v0.y, v0.y);
                xa[4*cc+2] = f2pack(v0.z, v0.z); xa[4*cc+3] = f2pack(v0.w, v0.w);
                xb[4*cc+0] = f2pack(v1.x, v1.x); xb[4*cc+1] = f2pack(v1.y, v1.y);
                xb[4*cc+2] = f2pack(v1.z, v1.z); xb[4*cc+3] = f2pack(v1.w, v1.w);
            }
        }

        float4* Zo0 = g_Z4 + (size_t)n0 * 20;
        float4* Zo1 = g_Z4 + (size_t)n1 * 20;
        const int d0 = r ? 5 : 0;
        const int d1 = r ? 9 : 5;
        #pragma unroll 1
        for (int d = d0; d < d1; d++) {
            const ulonglong2* Wd = (const ulonglong2*)(sWB + d * 64);
            __half2 ha[8], hb[8];
            #pragma unroll
            for (int oc = 0; oc < 4; oc++) {
                unsigned long long a0 = 0ull, a1 = 0ull;  // node0
                unsigned long long b0 = 0ull, b1 = 0ull;  // node1
                #pragma unroll
                for (int i = 0; i < 16; i++) {
                    ulonglong2 w = Wd[i * 4 + oc];
                    a0 = ffma2(xa[i], w.x, a0);
                    a1 = ffma2(xa[i], w.y, a1);
                    b0 = ffma2(xb[i], w.x, b0);
                    b1 = ffma2(xb[i], w.y, b1);
                }
                float f0, f1, f2, f3;
                f2unpack(a0, f0, f1); f2unpack(a1, f2, f3);
                ha[2*oc+0] = __floats2half2_rn(f0, f1);
                ha[2*oc+1] = __floats2half2_rn(f2, f3);
                f2unpack(b0, f0, f1); f2unpack(b1, f2, f3);
                hb[2*oc+0] = __floats2half2_rn(f0, f1);
                hb[2*oc+1] = __floats2half2_rn(f2, f3);
            }
            Zo0[d * 2 + 0] = *(float4*)&ha[0];
            Zo0[d * 2 + 1] = *(float4*)&ha[4];
            Zo1[d * 2 + 0] = *(float4*)&hb[0];
            Zo1[d * 2 + 1] = *(float4*)&hb[4];
        }

        if (r) {  // root term: agg_out[n] = x @ rootW + bias, for both nodes
            const ulonglong2* Rd = (const ulonglong2*)sR;
            float4* Ao0 = (float4*)(g_agg[layer & 1] + (size_t)n0 * 16);
            float4* Ao1 = (float4*)(g_agg[layer & 1] + (size_t)n1 * 16);
            #pragma unroll
            for (int oc = 0; oc < 4; oc++) {
                float4 bi = sBias[oc];
                unsigned long long a0 = f2pack(bi.x, bi.y);
                unsigned long long a1 = f2pack(bi.z, bi.w);
                unsigned long long b0 = a0, b1 = a1;
                #pragma unroll
                for (int i = 0; i < 16; i++) {
                    ulonglong2 w = Rd[i * 4 + oc];
                    a0 = ffma2(xa[i], w.x, a0);
                    a1 = ffma2(xa[i], w.y, a1);
                    b0 = ffma2(xb[i], w.x, b0);
                    b1 = ffma2(xb[i], w.y, b1);
                }
                float4 o;
                f2unpack(a0, o.x, o.y); f2unpack(a1, o.z, o.w);
                Ao0[oc] = o;
                f2unpack(b0, o.x, o.y); f2unpack(b1, o.z, o.w);
                Ao1[oc] = o;
            }
        }
    }
}

// ---------------------------------------------------------------------------
// edge: 4 threads per edge, NO shared memory, no __syncthreads.
//   Thread q loads float4 f = {q, 4+q, 8+q, 12+q} (+16+q if q<2):
//   d = (q>>1) + {0,2,4,6}, output half h = q&1.
//   Coefficients come pre-broadcast from g_pc[2e + (q>>1)] (one LDG.128).
//   Math: two 2-term HFMA2 chains combined in fp32; nnb added in fp32.
//   xor-2 shfl reduce; one red.v4.f32 per thread.
// ---------------------------------------------------------------------------
__global__ void __launch_bounds__(256) edge_kernel(int layer)
{
    const int gid = blockIdx.x * 256 + threadIdx.x;
    const int e   = gid >> 2;
    const int q   = gid & 3;
    const int hi  = q >> 1;

    const int2 sd = g_idx[e];
    const float4 cpack = g_pc[(size_t)e * 2 + hi];
    const __half2* cp = (const __half2*)&cpack;
    const __half2 c0 = cp[0], c1 = cp[1], c2 = cp[2], c3 = cp[3];

    const float4* zp = g_Z4 + (size_t)sd.x * 20 + q;
    float4 v0 = __ldcg(zp + 0);    // d = hi
    float4 v1 = __ldcg(zp + 4);    // d = 2+hi
    float4 v2 = __ldcg(zp + 8);    // d = 4+hi
    float4 v3 = __ldcg(zp + 12);   // d = 6+hi

    const __half2* h0 = (const __half2*)&v0;
    const __half2* h1 = (const __half2*)&v1;
    const __half2* h2 = (const __half2*)&v2;
    const __half2* h3 = (const __half2*)&v3;

    float m[8];
    #pragma unroll
    for (int j = 0; j < 4; j++) {
        __half2 t1 = __hfma2(c1, h1[j], __hmul2(c0, h0[j]));
        __half2 t2 = __hfma2(c3, h3[j], __hmul2(c2, h2[j]));
        float2 f1 = __half22float2(t1);
        float2 f2 = __half22float2(t2);
        m[2*j]   = f1.x + f2.x;
        m[2*j+1] = f1.y + f2.y;
    }

    if (q < 2) {  // nnb term (d=8, coefficient 1), added in fp32
        float4 vb = __ldcg(zp + 16);
        const __half2* hb = (const __half2*)&vb;
        #pragma unroll
        for (int j = 0; j < 4; j++) {
            float2 t = __half22float2(hb[j]);
            m[2*j] += t.x; m[2*j+1] += t.y;
        }
    }

    // Cross-pair reduction (q <-> q^2: same output half q&1, other d's).
    // hi==0 keeps m[0..3] (sends m[4..7]); hi==1 keeps m[4..7].
    float r[4];
    #pragma unroll
    for (int i = 0; i < 4; i++) {
        float send = hi ? m[i] : m[4 + i];
        float recv = __shfl_xor_sync(0xffffffffu, send, 2);
        r[i] = m[hi * 4 + i] + recv;
    }

    float* ag = g_agg[layer & 1] + (size_t)sd.y * 16 + (q & 1) * 8 + hi * 4;
    asm volatile("red.global.add.v4.f32 [%0], {%1,%2,%3,%4};"
                 :: "l"(ag), "f"(r[0]), "f"(r[1]), "f"(r[2]), "f"(r[3]) : "memory");
}

// ---------------------------------------------------------------------------
// head: out[n] = relu(agg[n]) . head_W[0:16] + gf[:,n] . head_W[16:24] + head_b
// ---------------------------------------------------------------------------
__global__ void __launch_bounds__(256) head_kernel(
    const float* __restrict__ gf, const float* __restrict__ hW,
    const float* __restrict__ hb, float* __restrict__ out)
{
    const int n = blockIdx.x * 256 + threadIdx.x;
    if (n >= NN) return;

    const float4* ar = (const float4*)(g_agg[0] + (size_t)n * 16);  // layer 2 wrote buf 0
    float acc = hb[0];
    #pragma unroll
    for (int c = 0; c < 4; c++) {
        float4 v = ar[c];
        acc = fmaf(fmaxf(v.x, 0.f), hW[4*c+0], acc);
        acc = fmaf(fmaxf(v.y, 0.f), hW[4*c+1], acc);
        acc = fmaf(fmaxf(v.z, 0.f), hW[4*c+2], acc);
        acc = fmaf(fmaxf(v.w, 0.f), hW[4*c+3], acc);
    }
    #pragma unroll
    for (int g = 0; g < 8; g++)
        acc = fmaf(gf[(size_t)g * NN + n], hW[16 + g], acc);
    out[n] = acc;
}

extern "C" void kernel_launch(void* const* d_in, const int* in_sizes, int n_in,
                              void* d_out, int out_size)
{
    const float* x     = (const float*)d_in[0];
    const int*   ei    = (const int*)  d_in[1];
    const float* ea    = (const float*)d_in[2];
    const float* gf    = (const float*)d_in[3];
    const float* nnW   = (const float*)d_in[4];
    const float* nnb   = (const float*)d_in[5];
    const float* rootW = (const float*)d_in[6];
    const float* bias  = (const float*)d_in[7];
    const float* hW    = (const float*)d_in[8];
    const float* hb    = (const float*)d_in[9];
    float* out = (float*)d_out;

    pack_kernel<<<(NE + 255) / 256, 256>>>(ei, ea);
    for (int layer = 0; layer < 3; layer++) {
        prep_kernel<<<PREP_GRID, 256>>>(x, layer, nnW, nnb, rootW, bias);
        edge_kernel<<<NE * 4 / 256, 256>>>(layer);
    }
    head_kernel<<<(NN + 255) / 256, 256>>>(gf, hW, hb, out);
}

// round 14
// speedup vs baseline: 1.1128x; 1.1128x over previous
#include <cuda_runtime.h>
#include <cuda_fp16.h>

#define NN 50000
#define NE 800000
#define HN 25000        // node pairs: pair p handles nodes p and p+HN
#define PREP0_BLOCKS 196  // ceil(25000/128) prep blocks inside fused kernel
#define PACK_BLOCKS  3125 // 800000/256

// Scratch (device globals — no allocation allowed in kernel_launch).
// g_Z4: per-node Z padded to 320B (20 float4): float4 index f=2d+h holds fp16
// Z[d][h*8..h*8+7], d=0..7 from nnW, d=8 from nnb; f=18,19 unused padding.
__device__ float4 g_Z4[(size_t)NN * 20];
__device__ float  g_agg[2][(size_t)NN * 16];  // ping-pong node feature buffers
// Packed per-edge data (built once by the fused kernel's pack blocks):
// g_pc[2e+hi] = 4 pre-broadcast half2 coefficients {c,c} for d = hi,2+hi,4+hi,6+hi
__device__ float4 g_pc[(size_t)NE * 2];
__device__ int2   g_idx[(size_t)NE];          // (src, dst)

// ---- packed f32x2 helpers (FFMA2: 2 fp32 FMAs per instruction, exact) ----
__device__ __forceinline__ unsigned long long f2pack(float lo, float hi) {
    unsigned long long d;
    asm("mov.b64 %0, {%1, %2};" : "=l"(d) : "f"(lo), "f"(hi));
    return d;
}
__device__ __forceinline__ void f2unpack(unsigned long long v, float& lo, float& hi) {
    asm("mov.b64 {%0, %1}, %2;" : "=f"(lo), "=f"(hi) : "l"(v));
}
__device__ __forceinline__ unsigned long long ffma2(
    unsigned long long a, unsigned long long b, unsigned long long c) {
    unsigned long long d;
    asm("fma.rn.f32x2 %0, %1, %2, %3;" : "=l"(d) : "l"(a), "l"(b), "l"(c));
    return d;
}

// ---------------------------------------------------------------------------
// Core prep math for one pair (n0, n1): Z rows [d0,d1) + optional root term.
// Weight quads amortized over 2 nodes; f32x2 packed FMA (exact fp32).
// ---------------------------------------------------------------------------
__device__ __forceinline__ void prep_pair(
    const float* __restrict__ xin, int n0, int n1, int r, bool relu,
    const float4* sWB, const float4* sR, const float4* sBias, float* aggOut)
{
    unsigned long long xa[16], xb[16];
    {
        const float4* xr0 = (const float4*)(xin + (size_t)n0 * 16);
        const float4* xr1 = (const float4*)(xin + (size_t)n1 * 16);
        #pragma unroll
        for (int cc = 0; cc < 4; cc++) {
            float4 v0 = xr0[cc];
            float4 v1 = xr1[cc];
            if (relu) {
                v0.x = fmaxf(v0.x, 0.f); v0.y = fmaxf(v0.y, 0.f);
                v0.z = fmaxf(v0.z, 0.f); v0.w = fmaxf(v0.w, 0.f);
                v1.x = fmaxf(v1.x, 0.f); v1.y = fmaxf(v1.y, 0.f);
                v1.z = fmaxf(v1.z, 0.f); v1.w = fmaxf(v1.w, 0.f);
            }
            xa[4*cc+0] = f2pack(v0.x, v0.x); xa[4*cc+1] = f2pack(v0.y, v0.y);
            xa[4*cc+2] = f2pack(v0.z, v0.z); xa[4*cc+3] = f2pack(v0.w, v0.w);
            xb[4*cc+0] = f2pack(v1.x, v1.x); xb[4*cc+1] = f2pack(v1.y, v1.y);
            xb[4*cc+2] = f2pack(v1.z, v1.z); xb[4*cc+3] = f2pack(v1.w, v1.w);
        }
    }

    float4* Zo0 = g_Z4 + (size_t)n0 * 20;
    float4* Zo1 = g_Z4 + (size_t)n1 * 20;
    const int d0 = r ? 5 : 0;
    const int d1 = r ? 9 : 5;
    #pragma unroll 1
    for (int d = d0; d < d1; d++) {
        const ulonglong2* Wd = (const ulonglong2*)(sWB + d * 64);
        __half2 ha[8], hb[8];
        #pragma unroll
        for (int oc = 0; oc < 4; oc++) {
            unsigned long long a0 = 0ull, a1 = 0ull;
            unsigned long long b0 = 0ull, b1 = 0ull;
            #pragma unroll
            for (int i = 0; i < 16; i++) {
                ulonglong2 w = Wd[i * 4 + oc];
                a0 = ffma2(xa[i], w.x, a0);
                a1 = ffma2(xa[i], w.y, a1);
                b0 = ffma2(xb[i], w.x, b0);
                b1 = ffma2(xb[i], w.y, b1);
            }
            float f0, f1, f2, f3;
            f2unpack(a0, f0, f1); f2unpack(a1, f2, f3);
            ha[2*oc+0] = __floats2half2_rn(f0, f1);
            ha[2*oc+1] = __floats2half2_rn(f2, f3);
            f2unpack(b0, f0, f1); f2unpack(b1, f2, f3);
            hb[2*oc+0] = __floats2half2_rn(f0, f1);
            hb[2*oc+1] = __floats2half2_rn(f2, f3);
        }
        Zo0[d * 2 + 0] = *(float4*)&ha[0];
        Zo0[d * 2 + 1] = *(float4*)&ha[4];
        Zo1[d * 2 + 0] = *(float4*)&hb[0];
        Zo1[d * 2 + 1] = *(float4*)&hb[4];
    }

    if (r) {  // root term: agg_out[n] = x @ rootW + bias, for both nodes
        const ulonglong2* Rd = (const ulonglong2*)sR;
        float4* Ao0 = (float4*)(aggOut + (size_t)n0 * 16);
        float4* Ao1 = (float4*)(aggOut + (size_t)n1 * 16);
        #pragma unroll
        for (int oc = 0; oc < 4; oc++) {
            float4 bi = sBias[oc];
            unsigned long long a0 = f2pack(bi.x, bi.y);
            unsigned long long a1 = f2pack(bi.z, bi.w);
            unsigned long long b0 = a0, b1 = a1;
            #pragma unroll
            for (int i = 0; i < 16; i++) {
                ulonglong2 w = Rd[i * 4 + oc];
                a0 = ffma2(xa[i], w.x, a0);
                a1 = ffma2(xa[i], w.y, a1);
                b0 = ffma2(xb[i], w.x, b0);
                b1 = ffma2(xb[i], w.y, b1);
            }
            float4 o;
            f2unpack(a0, o.x, o.y); f2unpack(a1, o.z, o.w);
            Ao0[oc] = o;
            f2unpack(b0, o.x, o.y); f2unpack(b1, o.z, o.w);
            Ao1[oc] = o;
        }
    }
}

// ---------------------------------------------------------------------------
// fused0: blocks [0,PREP0_BLOCKS) run prep for layer 0 (256 thr = 8 warps =
// 4 pair-groups x 2 roles, 128 pairs/block, no relu); remaining blocks run
// the one-time edge_attr pack + (src,dst) pack. The two are independent and
// both must finish before edge layer 0 — fusing overlaps pack's bandwidth
// work with prep's latency bubbles instead of serializing them.
// ---------------------------------------------------------------------------
__global__ void __launch_bounds__(256) fused0_kernel(
    const float* __restrict__ x, const int* __restrict__ ei,
    const float* __restrict__ ea,
    const float* __restrict__ nnW, const float* __restrict__ nnb,
    const float* __restrict__ rootW, const float* __restrict__ bias)
{
    if (blockIdx.x >= PREP0_BLOCKS) {
        // ---- pack block ----
        const int e = (blockIdx.x - PREP0_BLOCKS) * 256 + threadIdx.x;
        if (e >= NE) return;
        const float4 a = ((const float4*)ea)[(size_t)e * 2 + 0];  // c0..c3
        const float4 b = ((const float4*)ea)[(size_t)e * 2 + 1];  // c4..c7
        __half2 h0[4] = { __float2half2_rn(a.x), __float2half2_rn(a.z),
                          __float2half2_rn(b.x), __float2half2_rn(b.z) };
        __half2 h1[4] = { __float2half2_rn(a.y), __float2half2_rn(a.w),
                          __float2half2_rn(b.y), __float2half2_rn(b.w) };
        g_pc[(size_t)e * 2 + 0] = *(float4*)h0;
        g_pc[(size_t)e * 2 + 1] = *(float4*)h1;
        g_idx[e] = make_int2(ei[e], ei[NE + e]);
        return;
    }

    // ---- prep block, layer 0 ----
    __shared__ float4 sWB[576];
    __shared__ float4 sR[64];
    __shared__ float4 sBias[4];

    const int tid = threadIdx.x;
    {
        const float4* W4  = (const float4*)nnW;
        const float4* B4  = (const float4*)nnb;
        const float4* R4  = (const float4*)rootW;
        const float4* Bi4 = (const float4*)bias;
        #pragma unroll
        for (int j = tid; j < 512; j += 256) sWB[j] = W4[j];
        if (tid < 64) { sWB[512 + tid] = B4[tid]; sR[tid] = R4[tid]; }
        if (tid < 4)  sBias[tid] = Bi4[tid];
    }
    __syncthreads();

    const int warp = tid >> 5;
    const int lane = tid & 31;
    const int p    = blockIdx.x * 128 + (warp >> 1) * 32 + lane;
    if (p >= HN) return;
    prep_pair(x, p, p + HN, warp & 1, false, sWB, sR, sBias, g_agg[0]);
}

// ---------------------------------------------------------------------------
// prep (layers 1,2): R12 config — 391 blocks x 128 thr, warp-uniform d-split,
// 2 nodes/thread, relu on input.
// ---------------------------------------------------------------------------
__global__ void __launch_bounds__(128) prep_kernel(
    int layer,
    const float* __restrict__ nnW, const float* __restrict__ nnb,
    const float* __restrict__ rootW, const float* __restrict__ bias)
{
    __shared__ float4 sWB[576];
    __shared__ float4 sR[64];
    __shared__ float4 sBias[4];

    const int tid = threadIdx.x;
    {
        const float4* W4  = (const float4*)(nnW   + (size_t)layer * 2048);
        const float4* B4  = (const float4*)(nnb   + (size_t)layer * 256);
        const float4* R4  = (const float4*)(rootW + (size_t)layer * 256);
        const float4* Bi4 = (const float4*)(bias  + (size_t)layer * 16);
        #pragma unroll
        for (int j = tid; j < 512; j += 128) sWB[j] = W4[j];
        for (int j = tid; j < 64;  j += 128) { sWB[512 + j] = B4[j]; sR[j] = R4[j]; }
        if (tid < 4) sBias[tid] = Bi4[tid];
    }
    __syncthreads();

    const int warp = tid >> 5;
    const int lane = tid & 31;
    const int p    = blockIdx.x * 64 + (warp >> 1) * 32 + lane;
    if (p >= HN) return;
    prep_pair(g_agg[(layer - 1) & 1], p, p + HN, warp & 1, true,
              sWB, sR, sBias, g_agg[layer & 1]);
}

// ---------------------------------------------------------------------------
// edge: 4 threads per edge, NO shared memory (best measured config).
//   Thread q loads float4 f = {q, 4+q, 8+q, 12+q} (+16+q if q<2):
//   d = (q>>1) + {0,2,4,6}, output half h = q&1.
//   Coefficients pre-broadcast from g_pc[2e + (q>>1)] (one LDG.128).
//   Two 2-term HFMA2 chains combined in fp32; nnb added in fp32.
//   xor-2 shfl reduce; one red.v4.f32 per thread.
// ---------------------------------------------------------------------------
__global__ void __launch_bounds__(256) edge_kernel(int layer)
{
    const int gid = blockIdx.x * 256 + threadIdx.x;
    const int e   = gid >> 2;
    const int q   = gid & 3;
    const int hi  = q >> 1;

    const int2 sd = g_idx[e];
    const float4 cpack = g_pc[(size_t)e * 2 + hi];
    const __half2* cp = (const __half2*)&cpack;
    const __half2 c0 = cp[0], c1 = cp[1], c2 = cp[2], c3 = cp[3];

    const float4* zp = g_Z4 + (size_t)sd.x * 20 + q;
    float4 v0 = __ldcg(zp + 0);
    float4 v1 = __ldcg(zp + 4);
    float4 v2 = __ldcg(zp + 8);
    float4 v3 = __ldcg(zp + 12);

    const __half2* h0 = (const __half2*)&v0;
    const __half2* h1 = (const __half2*)&v1;
    const __half2* h2 = (const __half2*)&v2;
    const __half2* h3 = (const __half2*)&v3;

    float m[8];
    #pragma unroll
    for (int j = 0; j < 4; j++) {
        __half2 t1 = __hfma2(c1, h1[j], __hmul2(c0, h0[j]));
        __half2 t2 = __hfma2(c3, h3[j], __hmul2(c2, h2[j]));
        float2 f1 = __half22float2(t1);
        float2 f2 = __half22float2(t2);
        m[2*j]   = f1.x + f2.x;
        m[2*j+1] = f1.y + f2.y;
    }

    if (q < 2) {
        float4 vb = __ldcg(zp + 16);
        const __half2* hb = (const __half2*)&vb;
        #pragma unroll
        for (int j = 0; j < 4; j++) {
            float2 t = __half22float2(hb[j]);
            m[2*j] += t.x; m[2*j+1] += t.y;
        }
    }

    float r[4];
    #pragma unroll
    for (int i = 0; i < 4; i++) {
        float send = hi ? m[i] : m[4 + i];
        float recv = __shfl_xor_sync(0xffffffffu, send, 2);
        r[i] = m[hi * 4 + i] + recv;
    }

    float* ag = g_agg[layer & 1] + (size_t)sd.y * 16 + (q & 1) * 8 + hi * 4;
    asm volatile("red.global.add.v4.f32 [%0], {%1,%2,%3,%4};"
                 :: "l"(ag), "f"(r[0]), "f"(r[1]), "f"(r[2]), "f"(r[3]) : "memory");
}

// ---------------------------------------------------------------------------
// head: out[n] = relu(agg[n]) . head_W[0:16] + gf[:,n] . head_W[16:24] + head_b
// ---------------------------------------------------------------------------
__global__ void __launch_bounds__(256) head_kernel(
    const float* __restrict__ gf, const float* __restrict__ hW,
    const float* __restrict__ hb, float* __restrict__ out)
{
    const int n = blockIdx.x * 256 + threadIdx.x;
    if (n >= NN) return;

    const float4* ar = (const float4*)(g_agg[0] + (size_t)n * 16);  // layer 2 wrote buf 0
    float acc = hb[0];
    #pragma unroll
    for (int c = 0; c < 4; c++) {
        float4 v = ar[c];
        acc = fmaf(fmaxf(v.x, 0.f), hW[4*c+0], acc);
        acc = fmaf(fmaxf(v.y, 0.f), hW[4*c+1], acc);
        acc = fmaf(fmaxf(v.z, 0.f), hW[4*c+2], acc);
        acc = fmaf(fmaxf(v.w, 0.f), hW[4*c+3], acc);
    }
    #pragma unroll
    for (int g = 0; g < 8; g++)
        acc = fmaf(gf[(size_t)g * NN + n], hW[16 + g], acc);
    out[n] = acc;
}

extern "C" void kernel_launch(void* const* d_in, const int* in_sizes, int n_in,
                              void* d_out, int out_size)
{
    const float* x     = (const float*)d_in[0];
    const int*   ei    = (const int*)  d_in[1];
    const float* ea    = (const float*)d_in[2];
    const float* gf    = (const float*)d_in[3];
    const float* nnW   = (const float*)d_in[4];
    const float* nnb   = (const float*)d_in[5];
    const float* rootW = (const float*)d_in[6];
    const float* bias  = (const float*)d_in[7];
    const float* hW    = (const float*)d_in[8];
    const float* hb    = (const float*)d_in[9];
    float* out = (float*)d_out;

    fused0_kernel<<<PREP0_BLOCKS + PACK_BLOCKS, 256>>>(x, ei, ea, nnW, nnb, rootW, bias);
    edge_kernel<<<NE * 4 / 256, 256>>>(0);
    prep_kernel<<<(HN + 63) / 64, 128>>>(1, nnW, nnb, rootW, bias);
    edge_kernel<<<NE * 4 / 256, 256>>>(1);
    prep_kernel<<<(HN + 63) / 64, 128>>>(2, nnW, nnb, rootW, bias);
    edge_kernel<<<NE * 4 / 256, 256>>>(2);
    head_kernel<<<(NN + 255) / 256, 256>>>(gf, hW, hb, out);
}